// round 4
// baseline (speedup 1.0000x reference)
#include <cuda_runtime.h>
#include <cstdint>

#define B 64
#define C 256
#define CS 64
#define NC 8
#define BC (B * C)          // 16384 rows of 4096 floats
#define GRID 1024
#define ROWS_PER_BLK 16     // 16384 / 1024; all 16 rows belong to one sample

// Scratch (device globals: no allocation allowed)
__device__ float g_sum[BC];
__device__ float g_min[BC];
__device__ float g_max[BC];
__device__ float g_scale[BC];
__device__ float g_smin[B];
__device__ float g_smax[B];
__device__ unsigned g_barA;
__device__ unsigned g_barB;

__global__ void init_kernel() {
    g_barA = 0;
    g_barB = 0;
}

__device__ __forceinline__ void grid_barrier(unsigned* ctr) {
    __syncthreads();
    if (threadIdx.x == 0) {
        __threadfence();                 // make phase writes visible
        atomicAdd(ctr, 1u);
        unsigned v;
        do {
            asm volatile("ld.global.acquire.gpu.u32 %0, [%1];"
                         : "=r"(v) : "l"(ctr));
            if (v >= GRID) break;
            __nanosleep(64);
        } while (true);
    }
    __syncthreads();
}

__device__ __forceinline__ float quant_one(float xv, float m1, float zz,
                                           float ss, float c2) {
    float y = __fmaf_rn(xv, m1, zz);
    y = fminf(fmaxf(y, 0.0f), 255.0f);
    // round-to-nearest-even via magic add, y in [0,255]
    float q = __fadd_rn(__fadd_rn(y, 12582912.0f), -12582912.0f);
    return __fmaf_rn(q, ss, c2);
}

__global__ __launch_bounds__(256, 7) void fused_kernel(
    const float* __restrict__ x,
    const float* __restrict__ w1, const float* __restrict__ b1,
    const float* __restrict__ w2, const float* __restrict__ b2,
    const float* __restrict__ ar, const int* __restrict__ cl,
    float* __restrict__ out)
{
    const int t = threadIdx.x;
    const int w = t >> 5, lane = t & 31;
    const int base = blockIdx.x * ROWS_PER_BLK;   // first bc row of this block
    const int b = blockIdx.x >> 4;                // sample index (16 blocks/sample)

    // ---------------- Phase 1: per-row sum / min / max (warp per row) -------
    // Warp w owns rows 2w and 2w+1; reads ascending so row 2w+1 is the most
    // recently cached (phase 3 revisits in reverse).
#pragma unroll
    for (int rr = 0; rr < 2; ++rr) {
        const int bc = base + 2 * w + rr;
        const float4* p = reinterpret_cast<const float4*>(x) + (size_t)bc * 1024;
        float s = 0.0f, mn = 3.4028235e38f, mx = -3.4028235e38f;
#pragma unroll 8
        for (int k = 0; k < 32; ++k) {
            float4 v = p[lane + (k << 5)];
            s += (v.x + v.y) + (v.z + v.w);
            mn = fminf(mn, fminf(fminf(v.x, v.y), fminf(v.z, v.w)));
            mx = fmaxf(mx, fmaxf(fmaxf(v.x, v.y), fmaxf(v.z, v.w)));
        }
#pragma unroll
        for (int o = 16; o; o >>= 1) {
            s += __shfl_xor_sync(0xFFFFFFFFu, s, o);
            mn = fminf(mn, __shfl_xor_sync(0xFFFFFFFFu, mn, o));
            mx = fmaxf(mx, __shfl_xor_sync(0xFFFFFFFFu, mx, o));
        }
        if (lane == 0) {
            g_sum[bc] = s;
            g_min[bc] = mn;
            g_max[bc] = mx;
        }
    }

    grid_barrier(&g_barA);

    // ---------------- Phase 2: SE MLP, blocks 0..63 (one sample each) -------
    if (blockIdx.x < B) {
        const int sb = blockIdx.x;
        __shared__ __align__(16) float sp[C];
        __shared__ __align__(16) float sh_[CS];
        __shared__ float rmn[8], rmx[8];

        sp[t] = g_sum[sb * C + t] * (1.0f / 4096.0f);
        __syncthreads();

        // Hidden layer: warp w computes s = w*8 .. w*8+7
#pragma unroll
        for (int si = 0; si < 8; ++si) {
            const int s = w * 8 + si;
            const float4* wrow = reinterpret_cast<const float4*>(w1 + s * C);
            const float4* pr = reinterpret_cast<const float4*>(sp);
            float acc = 0.0f;
#pragma unroll
            for (int j = 0; j < 2; ++j) {
                float4 wv = wrow[lane + j * 32];
                float4 pv = pr[lane + j * 32];
                acc += wv.x * pv.x + wv.y * pv.y + wv.z * pv.z + wv.w * pv.w;
            }
#pragma unroll
            for (int o = 16; o; o >>= 1) acc += __shfl_xor_sync(0xFFFFFFFFu, acc, o);
            if (lane == 0) sh_[s] = fmaxf(acc + b1[s], 0.0f);
        }
        __syncthreads();

        // Output layer: thread t = channel c
        const int c = t;
        float v = b2[c];
        const float4* w2r = reinterpret_cast<const float4*>(w2 + c * CS);
        const float4* hr = reinterpret_cast<const float4*>(sh_);
#pragma unroll
        for (int j = 0; j < 16; ++j) {
            float4 wv = w2r[j];
            float4 hv = hr[j];
            v += wv.x * hv.x + wv.y * hv.y + wv.z * hv.z + wv.w * hv.w;
        }
        const float sc = __saturatef(v / 6.0f + 0.5f);
        const int idx = sb * C + c;
        g_scale[idx] = sc;
        float pmn = sc * g_min[idx];   // scale >= 0
        float pmx = sc * g_max[idx];
#pragma unroll
        for (int o = 16; o; o >>= 1) {
            pmn = fminf(pmn, __shfl_xor_sync(0xFFFFFFFFu, pmn, o));
            pmx = fmaxf(pmx, __shfl_xor_sync(0xFFFFFFFFu, pmx, o));
        }
        if (lane == 0) { rmn[w] = pmn; rmx[w] = pmx; }
        __syncthreads();
        if (t == 0) {
            float a = rmn[0], m = rmx[0];
#pragma unroll
            for (int i = 1; i < 8; ++i) { a = fminf(a, rmn[i]); m = fmaxf(m, rmx[i]); }
            g_smin[sb] = a;
            g_smax[sb] = m;
        }
    }

    grid_barrier(&g_barB);

    // ---------------- Phase 3: quant params (redundant per block) + quant ---
    const int k = cl[b];
    float cmn = 3.4028235e38f, cmx = -3.4028235e38f;
#pragma unroll 8
    for (int s = 0; s < B; ++s)
        if (cl[s] == k) {
            cmn = fminf(cmn, g_smin[s]);
            cmx = fmaxf(cmx, g_smax[s]);
        }
    const float nmn = ar[2 * k] * 0.995f + cmn * (1.0f - 0.995f);
    const float nmx = ar[2 * k + 1] * 0.995f + cmx * (1.0f - 0.995f);
    const float ss = (nmx - nmn) / 255.0f;
    const float zz = -rintf(nmn / ss);
    const float c2 = -zz * ss;        // (q - z)*s = fma(q, s, -z*s)
    const float inv = 1.0f / ss;

    // Reverse phase-1 order: row 2w+1 (freshest in L1/L2) first, then 2w.
#pragma unroll
    for (int rr = 1; rr >= 0; --rr) {
        const int bc = base + 2 * w + rr;
        const float m1 = g_scale[bc] * inv;       // scale / s (per channel)
        const float4* px = reinterpret_cast<const float4*>(x) + (size_t)bc * 1024;
        float4* po = reinterpret_cast<float4*>(out) + (size_t)bc * 1024;
#pragma unroll 8
        for (int kk = 0; kk < 32; ++kk) {
            float4 v = px[lane + (kk << 5)];
            float4 o;
            o.x = quant_one(v.x, m1, zz, ss, c2);
            o.y = quant_one(v.y, m1, zz, ss, c2);
            o.z = quant_one(v.z, m1, zz, ss, c2);
            o.w = quant_one(v.w, m1, zz, ss, c2);
            __stcs(&po[lane + (kk << 5)], o);
        }
    }
}

extern "C" void kernel_launch(void* const* d_in, const int* in_sizes, int n_in,
                              void* d_out, int out_size) {
    (void)in_sizes; (void)n_in; (void)out_size;
    const float* x  = (const float*)d_in[0];
    const float* w1 = (const float*)d_in[1];
    const float* b1 = (const float*)d_in[2];
    const float* w2 = (const float*)d_in[3];
    const float* b2 = (const float*)d_in[4];
    const float* ar = (const float*)d_in[5];
    const int*   cl = (const int*)d_in[6];
    float* out = (float*)d_out;

    init_kernel<<<1, 1>>>();
    fused_kernel<<<GRID, 256>>>(x, w1, b1, w2, b2, ar, cl, out);
}

// round 5
// speedup vs baseline: 1.1940x; 1.1940x over previous
#include <cuda_runtime.h>
#include <cstdint>

#define B 64
#define C 256
#define CS 64
#define NC 8
#define BC (B * C)   // 16384

// Scratch (device globals: no allocation allowed)
__device__ float g_sum[BC];
__device__ float g_min[BC];
__device__ float g_max[BC];
__device__ float g_scale[BC];
__device__ float g_smin[B];
__device__ float g_smax[B];

// ---------------------------------------------------------------------------
// Kernel 1: per-(b,c) sum / min / max over 4096 spatial elements.
// One WARP per (b,c) row. __ldcg: allocate in L2 (feeds the reversed quant
// pass) but skip L1 (zero reuse there).
// ---------------------------------------------------------------------------
__global__ __launch_bounds__(256) void reduce_kernel(const float* __restrict__ x) {
    const int w = threadIdx.x >> 5;
    const int lane = threadIdx.x & 31;
    const int bc = (blockIdx.x << 3) + w;
    const float4* p = reinterpret_cast<const float4*>(x) + (size_t)bc * 1024;

    float s = 0.0f, mn = 3.4028235e38f, mx = -3.4028235e38f;
#pragma unroll 8
    for (int k = 0; k < 32; ++k) {
        float4 v = __ldcg(&p[lane + (k << 5)]);
        s += (v.x + v.y) + (v.z + v.w);
        mn = fminf(mn, fminf(fminf(v.x, v.y), fminf(v.z, v.w)));
        mx = fmaxf(mx, fmaxf(fmaxf(v.x, v.y), fmaxf(v.z, v.w)));
    }
#pragma unroll
    for (int o = 16; o; o >>= 1) {
        s += __shfl_xor_sync(0xFFFFFFFFu, s, o);
        mn = fminf(mn, __shfl_xor_sync(0xFFFFFFFFu, mn, o));
        mx = fmaxf(mx, __shfl_xor_sync(0xFFFFFFFFu, mx, o));
    }
    if (lane == 0) {
        g_sum[bc] = s;
        g_min[bc] = mn;
        g_max[bc] = mx;
    }
}

// ---------------------------------------------------------------------------
// Kernel 2: per-sample SE MLP + scale + per-sample min/max of (scale * x).
// 64 blocks (one per sample b) x 256 threads.
// ---------------------------------------------------------------------------
__global__ __launch_bounds__(256) void se_kernel(const float* __restrict__ w1,
                                                 const float* __restrict__ b1,
                                                 const float* __restrict__ w2,
                                                 const float* __restrict__ b2) {
    const int b = blockIdx.x;
    const int t = threadIdx.x;
    const int w = t >> 5, lane = t & 31;

    __shared__ __align__(16) float sp[C];
    __shared__ __align__(16) float sh_[CS];
    __shared__ float rmn[8], rmx[8];

    sp[t] = g_sum[b * C + t] * (1.0f / 4096.0f);
    __syncthreads();

    // Hidden layer: warp w computes s = w*8 .. w*8+7.
#pragma unroll
    for (int si = 0; si < 8; ++si) {
        const int s = w * 8 + si;
        const float4* wrow = reinterpret_cast<const float4*>(w1 + s * C);
        const float4* pr = reinterpret_cast<const float4*>(sp);
        float acc = 0.0f;
#pragma unroll
        for (int j = 0; j < 2; ++j) {
            float4 wv = wrow[lane + j * 32];
            float4 pv = pr[lane + j * 32];
            acc += wv.x * pv.x + wv.y * pv.y + wv.z * pv.z + wv.w * pv.w;
        }
#pragma unroll
        for (int o = 16; o; o >>= 1) acc += __shfl_xor_sync(0xFFFFFFFFu, acc, o);
        if (lane == 0) sh_[s] = fmaxf(acc + b1[s], 0.0f);
    }
    __syncthreads();

    // Output layer: thread t = channel c.
    const int c = t;
    float v = b2[c];
    const float4* w2r = reinterpret_cast<const float4*>(w2 + c * CS);
    const float4* hr = reinterpret_cast<const float4*>(sh_);
#pragma unroll
    for (int j = 0; j < 16; ++j) {
        float4 wv = w2r[j];
        float4 hv = hr[j];
        v += wv.x * hv.x + wv.y * hv.y + wv.z * hv.z + wv.w * hv.w;
    }
    const float sc = __saturatef(v / 6.0f + 0.5f);
    const int idx = b * C + c;
    g_scale[idx] = sc;
    float pmn = sc * g_min[idx];   // scale >= 0
    float pmx = sc * g_max[idx];
#pragma unroll
    for (int o = 16; o; o >>= 1) {
        pmn = fminf(pmn, __shfl_xor_sync(0xFFFFFFFFu, pmn, o));
        pmx = fmaxf(pmx, __shfl_xor_sync(0xFFFFFFFFu, pmx, o));
    }
    if (lane == 0) { rmn[w] = pmn; rmx[w] = pmx; }
    __syncthreads();
    if (t == 0) {
        float a = rmn[0], m = rmx[0];
#pragma unroll
        for (int i = 1; i < 8; ++i) { a = fminf(a, rmn[i]); m = fmaxf(m, rmx[i]); }
        g_smin[b] = a;
        g_smax[b] = m;
    }
}

// ---------------------------------------------------------------------------
// Kernel 3: fused cluster-EMA params + scale + fake-quant elementwise pass.
// Warp 0 computes the per-sample quant params (cluster min/max via shfl) and
// broadcasts via smem; then all 8 warps stream. REVERSED block order so the
// first waves hit the x lines reduce left in L2. Stores evict-first.
// ---------------------------------------------------------------------------
__device__ __forceinline__ float quant_one(float xv, float m1, float zz,
                                           float ss, float c2) {
    float y = __fmaf_rn(xv, m1, zz);
    y = fminf(fmaxf(y, 0.0f), 255.0f);
    // round-to-nearest-even via magic add, y in [0,255]
    float q = __fadd_rn(__fadd_rn(y, 12582912.0f), -12582912.0f);
    return __fmaf_rn(q, ss, c2);
}

__global__ __launch_bounds__(256) void quant_kernel(const float* __restrict__ x,
                                                    const float* __restrict__ ar,
                                                    const int* __restrict__ cl,
                                                    float* __restrict__ out) {
    const int bc = (BC - 1) - blockIdx.x;   // reverse order for L2 reuse
    const int b = bc >> 8;
    const int t = threadIdx.x;
    const int w = t >> 5, lane = t & 31;

    __shared__ float p_zz, p_ss, p_c2, p_inv;

    if (w == 0) {
        const int k = cl[b];
        float cmn = 3.4028235e38f, cmx = -3.4028235e38f;
#pragma unroll
        for (int j = 0; j < 2; ++j) {
            const int s = lane + (j << 5);
            if (cl[s] == k) {
                cmn = fminf(cmn, g_smin[s]);
                cmx = fmaxf(cmx, g_smax[s]);
            }
        }
#pragma unroll
        for (int o = 16; o; o >>= 1) {
            cmn = fminf(cmn, __shfl_xor_sync(0xFFFFFFFFu, cmn, o));
            cmx = fmaxf(cmx, __shfl_xor_sync(0xFFFFFFFFu, cmx, o));
        }
        if (lane == 0) {
            const float nmn = ar[2 * k] * 0.995f + cmn * (1.0f - 0.995f);
            const float nmx = ar[2 * k + 1] * 0.995f + cmx * (1.0f - 0.995f);
            const float s = (nmx - nmn) / 255.0f;
            const float z = -rintf(nmn / s);
            p_ss = s;
            p_zz = z;
            p_c2 = -z * s;       // (q - z)*s = fma(q, s, -z*s)
            p_inv = 1.0f / s;
        }
    }
    __syncthreads();

    const float zz = p_zz, ss = p_ss, c2 = p_c2;
    const float m1 = g_scale[bc] * p_inv;   // scale / s  (per channel)
    const float4* px = reinterpret_cast<const float4*>(x) + (size_t)bc * 1024;
    float4* po = reinterpret_cast<float4*>(out) + (size_t)bc * 1024;
#pragma unroll
    for (int k = 0; k < 4; ++k) {
        float4 v = px[t + (k << 8)];
        float4 o;
        o.x = quant_one(v.x, m1, zz, ss, c2);
        o.y = quant_one(v.y, m1, zz, ss, c2);
        o.z = quant_one(v.z, m1, zz, ss, c2);
        o.w = quant_one(v.w, m1, zz, ss, c2);
        __stcs(&po[t + (k << 8)], o);
    }
}

extern "C" void kernel_launch(void* const* d_in, const int* in_sizes, int n_in,
                              void* d_out, int out_size) {
    (void)in_sizes; (void)n_in; (void)out_size;
    const float* x  = (const float*)d_in[0];
    const float* w1 = (const float*)d_in[1];
    const float* b1 = (const float*)d_in[2];
    const float* w2 = (const float*)d_in[3];
    const float* b2 = (const float*)d_in[4];
    const float* ar = (const float*)d_in[5];
    const int*   cl = (const int*)d_in[6];
    float* out = (float*)d_out;

    reduce_kernel<<<BC / 8, 256>>>(x);
    se_kernel<<<B, 256>>>(w1, b1, w2, b2);
    quant_kernel<<<BC, 256>>>(x, ar, cl, out);
}